// round 14
// baseline (speedup 1.0000x reference)
#include <cuda_runtime.h>
#include <math.h>

#define B_SZ 32
#define T_SZ 1024
#define I_SZ 512
#define H_SZ 1024
#define DT_C 0.1f

typedef unsigned long long ull;

// ---------------- f32x2 packed-math helpers (Blackwell FFMA2) -------------
__device__ __forceinline__ ull ffma2(ull a, ull b, ull c) {
    ull d; asm("fma.rn.f32x2 %0, %1, %2, %3;" : "=l"(d) : "l"(a), "l"(b), "l"(c)); return d;
}
__device__ __forceinline__ ull fadd2(ull a, ull b) {
    ull d; asm("add.rn.f32x2 %0, %1, %2;" : "=l"(d) : "l"(a), "l"(b)); return d;
}
__device__ __forceinline__ ull pack2(float lo, float hi) {
    ull d; asm("mov.b64 %0, {%1, %2};" : "=l"(d) : "f"(lo), "f"(hi)); return d;
}
__device__ __forceinline__ float2 unpack2(ull v) {
    float2 r; asm("mov.b64 {%0, %1}, %2;" : "=f"(r.x), "=f"(r.y) : "l"(v)); return r;
}
// Acquire load for producer-flag polls (orders subsequent loads after flag).
__device__ __forceinline__ int ld_acq(const volatile int* p) {
    int v;
    asm volatile("ld.acquire.gpu.global.s32 %0, [%1];"
                 : "=r"(v) : "l"((const int*)p) : "memory");
    return v;
}

// ------------------------------------------------------------------
// Persistent-kernel global state
// g_hT: TRIPLE-buffered transposed hidden state: [3][H][B]  (k-major).
// Depth-3: the write at step t (buf (t+1)%3) only conflicts with reads
// at step t-2, which the staging poll (g_arrive[peer] >= t) already
// excludes -> no write-permission flags needed (R13-proven).
// g_arrive[blk]: h for step t+1 published (set end of step t).
// ------------------------------------------------------------------
#define RBLK 128
#define FPAD 32                      // ints per flag slot (128B line)
__device__ float g_hT[3][H_SZ * B_SZ];
__device__ volatile int g_arrive[RBLK * FPAD];

__global__ void reset_kernel() {
    int idx = blockIdx.x * blockDim.x + threadIdx.x;
    if (idx < H_SZ * B_SZ) g_hT[0][idx] = 0.0f;
    if (idx < RBLK * FPAD) g_arrive[idx] = 0;
}

// ------------------------------------------------------------------
// xW GEMM: C[M=B*T, H] = X[M, I] @ W[H, I]^T   (fp32, FFMA2 inner)
// 128x64 block tile, BK=16, 256 threads  (R8/R11-proven)
// ------------------------------------------------------------------
#define GBM 128
#define GBN 64
#define GBK 16

union F4U { float4 f4; ull u[2]; };

__global__ void __launch_bounds__(256) gemm_xw(
    const float* __restrict__ X, const float* __restrict__ W,
    float* __restrict__ C)
{
    __shared__ float Xs[GBK][GBM];
    __shared__ float Ws[GBK][GBN + 4];
    const int tid = threadIdx.x;
    const int tx = tid & 15;   // 16 -> N
    const int ty = tid >> 4;   // 16 -> M
    const int m0 = blockIdx.y * GBM;
    const int n0 = blockIdx.x * GBN;

    ull acc2[4][4];   // [m-pair p][n j]
#pragma unroll
    for (int p = 0; p < 4; p++)
#pragma unroll
        for (int j = 0; j < 4; j++) acc2[p][j] = 0ull;

    for (int k0 = 0; k0 < I_SZ; k0 += GBK) {
#pragma unroll
        for (int pp = 0; pp < 2; pp++) {
            int q = tid + pp * 256;
            int row = q >> 2, qc = q & 3;
            float4 v = *(const float4*)(X + (size_t)(m0 + row) * I_SZ + k0 + qc * 4);
            Xs[qc * 4 + 0][row] = v.x; Xs[qc * 4 + 1][row] = v.y;
            Xs[qc * 4 + 2][row] = v.z; Xs[qc * 4 + 3][row] = v.w;
        }
        {
            int row = tid >> 2, qc = tid & 3;
            float4 v = *(const float4*)(W + (size_t)(n0 + row) * I_SZ + k0 + qc * 4);
            Ws[qc * 4 + 0][row] = v.x; Ws[qc * 4 + 1][row] = v.y;
            Ws[qc * 4 + 2][row] = v.z; Ws[qc * 4 + 3][row] = v.w;
        }
        __syncthreads();
#pragma unroll
        for (int kk = 0; kk < GBK; kk++) {
            F4U a0, a1;
            a0.f4 = *(const float4*)&Xs[kk][ty * 8];
            a1.f4 = *(const float4*)&Xs[kk][ty * 8 + 4];
            float4 bv = *(const float4*)&Ws[kk][tx * 4];
            ull bd[4];
            bd[0] = pack2(bv.x, bv.x); bd[1] = pack2(bv.y, bv.y);
            bd[2] = pack2(bv.z, bv.z); bd[3] = pack2(bv.w, bv.w);
            ull a2[4] = {a0.u[0], a0.u[1], a1.u[0], a1.u[1]};
#pragma unroll
            for (int p = 0; p < 4; p++)
#pragma unroll
                for (int j = 0; j < 4; j++)
                    acc2[p][j] = ffma2(a2[p], bd[j], acc2[p][j]);
        }
        __syncthreads();
    }
#pragma unroll
    for (int p = 0; p < 4; p++) {
        float2 c0 = unpack2(acc2[p][0]);
        float2 c1 = unpack2(acc2[p][1]);
        float2 c2 = unpack2(acc2[p][2]);
        float2 c3 = unpack2(acc2[p][3]);
        float4 lo = make_float4(c0.x, c1.x, c2.x, c3.x);
        float4 hi = make_float4(c0.y, c1.y, c2.y, c3.y);
        *(float4*)(C + (size_t)(m0 + ty * 8 + 2 * p)     * H_SZ + n0 + tx * 4) = lo;
        *(float4*)(C + (size_t)(m0 + ty * 8 + 2 * p + 1) * H_SZ + n0 + tx * 4) = hi;
    }
}

// ------------------------------------------------------------------
// Persistent recurrence kernel (R13 + own-chunk smem shortcut).
// grid = 128 blocks (64 j-tiles x 2 b-halves), 512 threads.
// Own chunk (k rows 16jt..16jt+15) = this block's own epilogue output:
// written directly to hs, never re-read from global.
// Staging (63 peer chunks): warps 4-15 only --
//   wave1: threads 128-511, chunks jt+16..jt+63
//   wave2: threads 128-247, chunks jt+1..jt+15
// Warps 0-3: reduce + epilogue + flag, no staging.
// ------------------------------------------------------------------
#define JT 16
#define BHALF 16
#define USTR 1025
#define HSTR 20
#define NPO 128
#define RECUR_SMEM ((JT * USTR + H_SZ * HSTR) * 4 + NPO * 64 * 8)

__device__ __forceinline__ void stage_chunk(float* hs, int gbase, int bg0,
                                            int ch, int lc, int t_tgt,
                                            int buf) {
    const volatile int* pf = &g_arrive[(gbase | ch) * FPAD];
    while (ld_acq(pf) < t_tgt) { }
    const float* gsrc = g_hT[buf] + bg0 + (size_t)(16 * ch) * B_SZ;
    float* hdst = hs + (16 * ch) * HSTR;
#pragma unroll
    for (int i = 0; i < 8; i++) {
        int f = lc + 8 * i;                 // 0..63 float4s in chunk
        int row = f >> 2, part = (f & 3) * 4;
        float4 v = __ldcg((const float4*)(gsrc + (size_t)row * B_SZ + part));
        float* d = hdst + row * HSTR + part;
        d[0] = v.x; d[1] = v.y; d[2] = v.z; d[3] = v.w;
    }
}

__global__ void __launch_bounds__(512, 1) recur_kernel(
    float* __restrict__ states,      // [B, T, H] (holds xW on entry, states on exit)
    float* __restrict__ hfinal,      // [B, H]
    const float* __restrict__ U,     // [H, H]
    const float* __restrict__ bias,  // [H]
    const float* __restrict__ tau)   // [H]
{
    extern __shared__ float sm[];
    float* Us = sm;                                 // [JT][USTR]
    float* hs = Us + JT * USTR;                     // [1024][HSTR]
    ull* red = (ull*)(hs + H_SZ * HSTR);            // [NPO][64]

    const int tid = threadIdx.x;
    const int blk = blockIdx.x;
    const int jt = blk & 63;
    const int bh = blk >> 6;
    const int j0 = jt * JT;
    const int bg0 = bh * BHALF;
    const int gbase = bh << 6;        // first block of this flag group

    const int tb = tid & 1;
    const int tj = (tid >> 1) & 3;
    const int ks = tid >> 3;      // 0..63

    // ---- staging chunk assignment (warps 4-15 only) ----
    const int ch1 = (jt + 16 + ((tid - 128) >> 3)) & 63;   // tid>=128: 48 chunks
    const int ch2 = (jt + 1 + ((tid - 128) >> 3)) & 63;    // tid in [128,248): 15
    const int lc = tid & 7;

    // ---- load U slab into smem: Us[row][k], row = 0..15 ----
    for (int q = tid; q < JT * (H_SZ / 4); q += 512) {
        int row = q >> 8;
        int c = (q & 255) * 4;
        float4 v = *(const float4*)(U + (size_t)(j0 + row) * H_SZ + c);
        float* d = Us + row * USTR + c;
        d[0] = v.x; d[1] = v.y; d[2] = v.z; d[3] = v.w;
    }

    // ---- epilogue (reader) setup: tid < 128, sr = tid & 15 ----
    int po = 0, sr = 0, jg = 0, bp = 0;
    float decay = 0.0f, biasj = 0.0f;
    size_t sidx0 = 0, sidx1 = 0;
    float xwA = 0.0f, xwB = 0.0f;
    if (tid < NPO) {
        int r = tid;
        po = ((r >> 1) & 1) | ((r & 1) << 1) | (((r >> 4) & 1) << 2)
           | (((r >> 5) & 1) << 3) | (((r >> 6) & 1) << 4)
           | (((r >> 2) & 1) << 5) | (((r >> 3) & 1) << 6);
        sr = r & 15;
        int j_loc = po >> 3;
        bp = po & 7;
        jg = j0 + j_loc;
        float it = 1.0f / tau[jg];
        decay = 1.0f - DT_C * it;
        biasj = bias[jg];
        int b_glob = bg0 + 2 * bp;
        sidx0 = (size_t)b_glob * T_SZ * H_SZ + jg;
        sidx1 = sidx0 + (size_t)T_SZ * H_SZ;
        xwA = __ldcg(states + sidx0);   // prefetch t = 0
        xwB = __ldcg(states + sidx1);
        // own chunk is never staged from global: initialize h_0 = 0 rows
        hs[jg * HSTR + 2 * bp] = 0.0f;
        hs[jg * HSTR + 2 * bp + 1] = 0.0f;
    }

    int cur = 0;    // buffer index = t % 3
    __syncthreads();

    for (int t = 0; t < T_SZ; t++) {
        // ---- stage 63 peer chunks (warps 4-15); own chunk already in hs --
        if (tid >= 128) {
            stage_chunk(hs, gbase, bg0, ch1, lc, t, cur);
            if (tid < 248) stage_chunk(hs, gbase, bg0, ch2, lc, t, cur);
        }
        __syncthreads();

        // ---- compute: acc2[jj][m] over k = ks + 64*kq ----
        ull acc2[4][4];
#pragma unroll
        for (int jj = 0; jj < 4; jj++)
#pragma unroll
            for (int m = 0; m < 4; m++) acc2[jj][m] = 0ull;

        const float* urow = Us + tj * 4 * USTR + ks;
#pragma unroll
        for (int kq = 0; kq < 16; kq++) {
            int k = ks + 64 * kq;
            const float* hrow = hs + k * HSTR + 2 * tb;
            ull h0 = *(const ull*)(hrow + 0);
            ull h1 = *(const ull*)(hrow + 4);
            ull h2 = *(const ull*)(hrow + 8);
            ull h3 = *(const ull*)(hrow + 12);
#pragma unroll
            for (int jj = 0; jj < 4; jj++) {
                float us = urow[jj * USTR + 64 * kq];
                ull ud = pack2(us, us);
                acc2[jj][0] = ffma2(ud, h0, acc2[jj][0]);
                acc2[jj][1] = ffma2(ud, h1, acc2[jj][1]);
                acc2[jj][2] = ffma2(ud, h2, acc2[jj][2]);
                acc2[jj][3] = ffma2(ud, h3, acc2[jj][3]);
            }
        }

        // ---- write partials, XOR-swizzled (2-phase-optimal STS.64) ----
#pragma unroll
        for (int jj = 0; jj < 4; jj++)
#pragma unroll
            for (int m = 0; m < 4; m++) {
                int p = (tj * 4 + jj) * 8 + 2 * m + tb;
                int col = ks ^ ((m & 1) | (tb << 1) | (tj << 2));
                red[p * 64 + col] = acc2[jj][m];
            }
        __syncthreads();
        // Warps 4-15 are now done with step t and fall through to the next
        // iteration's staging (overlapping the epilogue). They touch only
        // peer chunks; warps 0-3 below read red + own chunk rows.

        int nxt = cur + 1; if (nxt == 3) nxt = 0;
        if (tid < NPO) {
            // ---- reduce ----
            ull s01 = 0ull, s23 = 0ull;
#pragma unroll
            for (int i = 0; i < 64; i += 2) {
                s01 = fadd2(s01, red[po * 64 + (i ^ sr)]);
                s23 = fadd2(s23, red[po * 64 + ((i + 1) ^ sr)]);
            }
            float2 sum = unpack2(fadd2(s01, s23));
            float2 hold = *(const float2*)(hs + jg * HSTR + 2 * bp);
            // ---- pointwise epilogue ----
            float a0 = tanhf(xwA + sum.x + biasj);
            float a1 = tanhf(xwB + sum.y + biasj);
            float h0n = decay * hold.x + DT_C * a0;
            float h1n = decay * hold.y + DT_C * a1;
            float2 hn = make_float2(h0n, h1n);
            // own chunk directly into smem for step t+1 (no global round trip)
            *(float2*)(hs + jg * HSTR + 2 * bp) = hn;
            // publish for the 63 peer blocks, then flag ASAP
            __stcg((float2*)(g_hT[nxt] + (size_t)jg * B_SZ + bg0 + 2 * bp), hn);
            asm volatile("bar.sync 1, 128;" ::: "memory");
            if (tid == 0) {
                __threadfence();
                g_arrive[blk * FPAD] = t + 1;
            }
            // non-published outputs after the flag (peers don't need these)
            size_t off = (size_t)t * H_SZ;
            __stcg(states + sidx0 + off, h0n);
            __stcg(states + sidx1 + off, h1n);
            if (t == T_SZ - 1) {
                __stcg(hfinal + (size_t)(bg0 + 2 * bp) * H_SZ + jg, h0n);
                __stcg(hfinal + (size_t)(bg0 + 2 * bp + 1) * H_SZ + jg, h1n);
            } else {
                xwA = __ldcg(states + sidx0 + off + H_SZ);   // prefetch t+1
                xwB = __ldcg(states + sidx1 + off + H_SZ);
            }
        }
        cur = nxt;
    }
}

// ------------------------------------------------------------------
// Launcher
// ------------------------------------------------------------------
extern "C" void kernel_launch(void* const* d_in, const int* in_sizes, int n_in,
                              void* d_out, int out_size) {
    const float* x   = (const float*)d_in[0];   // [B, T, I]
    const float* W   = (const float*)d_in[1];   // [H, I]
    const float* U   = (const float*)d_in[2];   // [H, H]
    const float* b   = (const float*)d_in[3];   // [H]
    const float* tau = (const float*)d_in[4];   // [H]

    float* hfinal = (float*)d_out;              // [B, H]
    float* states = hfinal + B_SZ * H_SZ;       // [B, T, H]

    cudaFuncSetAttribute(recur_kernel,
                         cudaFuncAttributeMaxDynamicSharedMemorySize,
                         RECUR_SMEM);

    reset_kernel<<<32, 1024>>>();

    dim3 ggrid(H_SZ / GBN, (B_SZ * T_SZ) / GBM);
    gemm_xw<<<ggrid, 256>>>(x, W, states);

    recur_kernel<<<RBLK, 512, RECUR_SMEM>>>(states, hfinal, U, b, tau);
}

// round 15
// speedup vs baseline: 1.2016x; 1.2016x over previous
#include <cuda_runtime.h>
#include <math.h>

#define B_SZ 32
#define T_SZ 1024
#define I_SZ 512
#define H_SZ 1024
#define DT_C 0.1f

typedef unsigned long long ull;

// ---------------- f32x2 packed-math helpers (Blackwell FFMA2) -------------
__device__ __forceinline__ ull ffma2(ull a, ull b, ull c) {
    ull d; asm("fma.rn.f32x2 %0, %1, %2, %3;" : "=l"(d) : "l"(a), "l"(b), "l"(c)); return d;
}
__device__ __forceinline__ ull fadd2(ull a, ull b) {
    ull d; asm("add.rn.f32x2 %0, %1, %2;" : "=l"(d) : "l"(a), "l"(b)); return d;
}
__device__ __forceinline__ ull pack2(float lo, float hi) {
    ull d; asm("mov.b64 %0, {%1, %2};" : "=l"(d) : "f"(lo), "f"(hi)); return d;
}
__device__ __forceinline__ float2 unpack2(ull v) {
    float2 r; asm("mov.b64 {%0, %1}, %2;" : "=f"(r.x), "=f"(r.y) : "l"(v)); return r;
}
// Acquire load for producer-flag polls (orders subsequent loads after flag).
__device__ __forceinline__ int ld_acq(const volatile int* p) {
    int v;
    asm volatile("ld.acquire.gpu.global.s32 %0, [%1];"
                 : "=r"(v) : "l"((const int*)p) : "memory");
    return v;
}

// ------------------------------------------------------------------
// Persistent-kernel global state
// g_hT: TRIPLE-buffered transposed hidden state: [3][H][B]  (k-major).
// Depth-3: the write at step t (buf (t+1)%3) only conflicts with reads
// at step t-2, which the staging poll (g_arrive[peer] >= t) already
// excludes -> no write-permission flags needed (R13-proven).
// g_arrive[blk]: h for step t+1 published (set end of step t).
// ------------------------------------------------------------------
#define RBLK 128
#define FPAD 32                      // ints per flag slot (128B line)
__device__ float g_hT[3][H_SZ * B_SZ];
__device__ volatile int g_arrive[RBLK * FPAD];

__global__ void reset_kernel() {
    int idx = blockIdx.x * blockDim.x + threadIdx.x;
    if (idx < H_SZ * B_SZ) g_hT[0][idx] = 0.0f;
    if (idx < RBLK * FPAD) g_arrive[idx] = 0;
}

// ------------------------------------------------------------------
// xW GEMM: C[M=B*T, H] = X[M, I] @ W[H, I]^T   (fp32, FFMA2 inner)
// 128x64 block tile, BK=16, 256 threads  (R8/R11-proven)
// ------------------------------------------------------------------
#define GBM 128
#define GBN 64
#define GBK 16

union F4U { float4 f4; ull u[2]; };

__global__ void __launch_bounds__(256) gemm_xw(
    const float* __restrict__ X, const float* __restrict__ W,
    float* __restrict__ C)
{
    __shared__ float Xs[GBK][GBM];
    __shared__ float Ws[GBK][GBN + 4];
    const int tid = threadIdx.x;
    const int tx = tid & 15;   // 16 -> N
    const int ty = tid >> 4;   // 16 -> M
    const int m0 = blockIdx.y * GBM;
    const int n0 = blockIdx.x * GBN;

    ull acc2[4][4];   // [m-pair p][n j]
#pragma unroll
    for (int p = 0; p < 4; p++)
#pragma unroll
        for (int j = 0; j < 4; j++) acc2[p][j] = 0ull;

    for (int k0 = 0; k0 < I_SZ; k0 += GBK) {
#pragma unroll
        for (int pp = 0; pp < 2; pp++) {
            int q = tid + pp * 256;
            int row = q >> 2, qc = q & 3;
            float4 v = *(const float4*)(X + (size_t)(m0 + row) * I_SZ + k0 + qc * 4);
            Xs[qc * 4 + 0][row] = v.x; Xs[qc * 4 + 1][row] = v.y;
            Xs[qc * 4 + 2][row] = v.z; Xs[qc * 4 + 3][row] = v.w;
        }
        {
            int row = tid >> 2, qc = tid & 3;
            float4 v = *(const float4*)(W + (size_t)(n0 + row) * I_SZ + k0 + qc * 4);
            Ws[qc * 4 + 0][row] = v.x; Ws[qc * 4 + 1][row] = v.y;
            Ws[qc * 4 + 2][row] = v.z; Ws[qc * 4 + 3][row] = v.w;
        }
        __syncthreads();
#pragma unroll
        for (int kk = 0; kk < GBK; kk++) {
            F4U a0, a1;
            a0.f4 = *(const float4*)&Xs[kk][ty * 8];
            a1.f4 = *(const float4*)&Xs[kk][ty * 8 + 4];
            float4 bv = *(const float4*)&Ws[kk][tx * 4];
            ull bd[4];
            bd[0] = pack2(bv.x, bv.x); bd[1] = pack2(bv.y, bv.y);
            bd[2] = pack2(bv.z, bv.z); bd[3] = pack2(bv.w, bv.w);
            ull a2[4] = {a0.u[0], a0.u[1], a1.u[0], a1.u[1]};
#pragma unroll
            for (int p = 0; p < 4; p++)
#pragma unroll
                for (int j = 0; j < 4; j++)
                    acc2[p][j] = ffma2(a2[p], bd[j], acc2[p][j]);
        }
        __syncthreads();
    }
#pragma unroll
    for (int p = 0; p < 4; p++) {
        float2 c0 = unpack2(acc2[p][0]);
        float2 c1 = unpack2(acc2[p][1]);
        float2 c2 = unpack2(acc2[p][2]);
        float2 c3 = unpack2(acc2[p][3]);
        float4 lo = make_float4(c0.x, c1.x, c2.x, c3.x);
        float4 hi = make_float4(c0.y, c1.y, c2.y, c3.y);
        *(float4*)(C + (size_t)(m0 + ty * 8 + 2 * p)     * H_SZ + n0 + tx * 4) = lo;
        *(float4*)(C + (size_t)(m0 + ty * 8 + 2 * p + 1) * H_SZ + n0 + tx * 4) = hi;
    }
}

// ------------------------------------------------------------------
// Persistent recurrence kernel (R13 staging topology + own-chunk
// smem shortcut + early flag).
// grid = 128 blocks (64 j-tiles x 2 b-halves), 512 threads.
// Staging (per step): warps 0-3 teams 1..15 stage chunks jt+1..jt+15
// (team 0 idle: own chunk is written directly by the epilogue);
// warps 4-15 stage chunks jt+16..jt+63 (overlapping the epilogue).
// ------------------------------------------------------------------
#define JT 16
#define BHALF 16
#define USTR 1025
#define HSTR 20
#define NPO 128
#define RECUR_SMEM ((JT * USTR + H_SZ * HSTR) * 4 + NPO * 64 * 8)

__device__ __forceinline__ void stage_chunk(float* hs, int gbase, int bg0,
                                            int ch, int lc, int t_tgt,
                                            int buf) {
    const volatile int* pf = &g_arrive[(gbase | ch) * FPAD];
    while (ld_acq(pf) < t_tgt) { }
    const float* gsrc = g_hT[buf] + bg0 + (size_t)(16 * ch) * B_SZ;
    float* hdst = hs + (16 * ch) * HSTR;
#pragma unroll
    for (int i = 0; i < 8; i++) {
        int f = lc + 8 * i;                 // 0..63 float4s in chunk
        int row = f >> 2, part = (f & 3) * 4;
        float4 v = __ldcg((const float4*)(gsrc + (size_t)row * B_SZ + part));
        float* d = hdst + row * HSTR + part;
        d[0] = v.x; d[1] = v.y; d[2] = v.z; d[3] = v.w;
    }
}

__global__ void __launch_bounds__(512, 1) recur_kernel(
    float* __restrict__ states,      // [B, T, H] (holds xW on entry, states on exit)
    float* __restrict__ hfinal,      // [B, H]
    const float* __restrict__ U,     // [H, H]
    const float* __restrict__ bias,  // [H]
    const float* __restrict__ tau)   // [H]
{
    extern __shared__ float sm[];
    float* Us = sm;                                 // [JT][USTR]
    float* hs = Us + JT * USTR;                     // [1024][HSTR]
    ull* red = (ull*)(hs + H_SZ * HSTR);            // [NPO][64]

    const int tid = threadIdx.x;
    const int blk = blockIdx.x;
    const int jt = blk & 63;
    const int bh = blk >> 6;
    const int j0 = jt * JT;
    const int bg0 = bh * BHALF;
    const int gbase = bh << 6;        // first block of this flag group

    const int tb = tid & 1;
    const int tj = (tid >> 1) & 3;
    const int ks = tid >> 3;      // 0..63

    // ---- staging chunk assignment (R13 topology; team 0 of warps 0-3
    //      is idle -- own chunk comes from the epilogue's smem write) ----
    const int ch = (tid < 128) ? ((jt + (tid >> 3)) & 63)
                               : ((jt + 16 + ((tid - 128) >> 3)) & 63);
    const int lc = tid & 7;
    const bool do_stage = (tid >= 128) || ((tid >> 3) != 0);

    // ---- load U slab into smem: Us[row][k], row = 0..15 ----
    for (int q = tid; q < JT * (H_SZ / 4); q += 512) {
        int row = q >> 8;
        int c = (q & 255) * 4;
        float4 v = *(const float4*)(U + (size_t)(j0 + row) * H_SZ + c);
        float* d = Us + row * USTR + c;
        d[0] = v.x; d[1] = v.y; d[2] = v.z; d[3] = v.w;
    }

    // ---- epilogue (reader) setup: tid < 128, sr = tid & 15 ----
    int po = 0, sr = 0, jg = 0, bp = 0;
    float decay = 0.0f, biasj = 0.0f;
    size_t sidx0 = 0, sidx1 = 0;
    float xwA = 0.0f, xwB = 0.0f;
    if (tid < NPO) {
        int r = tid;
        po = ((r >> 1) & 1) | ((r & 1) << 1) | (((r >> 4) & 1) << 2)
           | (((r >> 5) & 1) << 3) | (((r >> 6) & 1) << 4)
           | (((r >> 2) & 1) << 5) | (((r >> 3) & 1) << 6);
        sr = r & 15;
        int j_loc = po >> 3;
        bp = po & 7;
        jg = j0 + j_loc;
        float it = 1.0f / tau[jg];
        decay = 1.0f - DT_C * it;
        biasj = bias[jg];
        int b_glob = bg0 + 2 * bp;
        sidx0 = (size_t)b_glob * T_SZ * H_SZ + jg;
        sidx1 = sidx0 + (size_t)T_SZ * H_SZ;
        xwA = __ldcg(states + sidx0);   // prefetch t = 0
        xwB = __ldcg(states + sidx1);
        // own chunk is never staged from global: initialize h_0 = 0 rows
        hs[jg * HSTR + 2 * bp] = 0.0f;
        hs[jg * HSTR + 2 * bp + 1] = 0.0f;
    }

    int cur = 0;    // buffer index = t % 3
    __syncthreads();

    for (int t = 0; t < T_SZ; t++) {
        // ---- stage 63 peer chunks; own chunk already in hs ----
        if (do_stage) {
            stage_chunk(hs, gbase, bg0, ch, lc, t, cur);
        }
        __syncthreads();

        // ---- compute: acc2[jj][m] over k = ks + 64*kq ----
        ull acc2[4][4];
#pragma unroll
        for (int jj = 0; jj < 4; jj++)
#pragma unroll
            for (int m = 0; m < 4; m++) acc2[jj][m] = 0ull;

        const float* urow = Us + tj * 4 * USTR + ks;
#pragma unroll
        for (int kq = 0; kq < 16; kq++) {
            int k = ks + 64 * kq;
            const float* hrow = hs + k * HSTR + 2 * tb;
            ull h0 = *(const ull*)(hrow + 0);
            ull h1 = *(const ull*)(hrow + 4);
            ull h2 = *(const ull*)(hrow + 8);
            ull h3 = *(const ull*)(hrow + 12);
#pragma unroll
            for (int jj = 0; jj < 4; jj++) {
                float us = urow[jj * USTR + 64 * kq];
                ull ud = pack2(us, us);
                acc2[jj][0] = ffma2(ud, h0, acc2[jj][0]);
                acc2[jj][1] = ffma2(ud, h1, acc2[jj][1]);
                acc2[jj][2] = ffma2(ud, h2, acc2[jj][2]);
                acc2[jj][3] = ffma2(ud, h3, acc2[jj][3]);
            }
        }

        // ---- write partials, XOR-swizzled (2-phase-optimal STS.64) ----
#pragma unroll
        for (int jj = 0; jj < 4; jj++)
#pragma unroll
            for (int m = 0; m < 4; m++) {
                int p = (tj * 4 + jj) * 8 + 2 * m + tb;
                int col = ks ^ ((m & 1) | (tb << 1) | (tj << 2));
                red[p * 64 + col] = acc2[jj][m];
            }
        __syncthreads();
        // Warps 4-15 fall through to the next iteration's staging
        // (overlapping the epilogue). They touch only chunks jt+16..jt+63;
        // warps 0-3 below read red + own chunk rows only.

        int nxt = cur + 1; if (nxt == 3) nxt = 0;
        if (tid < NPO) {
            // ---- reduce ----
            ull s01 = 0ull, s23 = 0ull;
#pragma unroll
            for (int i = 0; i < 64; i += 2) {
                s01 = fadd2(s01, red[po * 64 + (i ^ sr)]);
                s23 = fadd2(s23, red[po * 64 + ((i + 1) ^ sr)]);
            }
            float2 sum = unpack2(fadd2(s01, s23));
            float2 hold = *(const float2*)(hs + jg * HSTR + 2 * bp);
            // ---- pointwise epilogue ----
            float a0 = tanhf(xwA + sum.x + biasj);
            float a1 = tanhf(xwB + sum.y + biasj);
            float h0n = decay * hold.x + DT_C * a0;
            float h1n = decay * hold.y + DT_C * a1;
            float2 hn = make_float2(h0n, h1n);
            // own chunk directly into smem for step t+1 (no global round trip)
            *(float2*)(hs + jg * HSTR + 2 * bp) = hn;
            // publish for peer blocks, then flag ASAP
            __stcg((float2*)(g_hT[nxt] + (size_t)jg * B_SZ + bg0 + 2 * bp), hn);
            asm volatile("bar.sync 1, 128;" ::: "memory");
            if (tid == 0) {
                __threadfence();
                g_arrive[blk * FPAD] = t + 1;
            }
            // non-published outputs after the flag (peers don't need these)
            size_t off = (size_t)t * H_SZ;
            __stcg(states + sidx0 + off, h0n);
            __stcg(states + sidx1 + off, h1n);
            if (t == T_SZ - 1) {
                __stcg(hfinal + (size_t)(bg0 + 2 * bp) * H_SZ + jg, h0n);
                __stcg(hfinal + (size_t)(bg0 + 2 * bp + 1) * H_SZ + jg, h1n);
            } else {
                xwA = __ldcg(states + sidx0 + off + H_SZ);   // prefetch t+1
                xwB = __ldcg(states + sidx1 + off + H_SZ);
            }
        }
        cur = nxt;
    }
}

// ------------------------------------------------------------------
// Launcher
// ------------------------------------------------------------------
extern "C" void kernel_launch(void* const* d_in, const int* in_sizes, int n_in,
                              void* d_out, int out_size) {
    const float* x   = (const float*)d_in[0];   // [B, T, I]
    const float* W   = (const float*)d_in[1];   // [H, I]
    const float* U   = (const float*)d_in[2];   // [H, H]
    const float* b   = (const float*)d_in[3];   // [H]
    const float* tau = (const float*)d_in[4];   // [H]

    float* hfinal = (float*)d_out;              // [B, H]
    float* states = hfinal + B_SZ * H_SZ;       // [B, T, H]

    cudaFuncSetAttribute(recur_kernel,
                         cudaFuncAttributeMaxDynamicSharedMemorySize,
                         RECUR_SMEM);

    reset_kernel<<<32, 1024>>>();

    dim3 ggrid(H_SZ / GBN, (B_SZ * T_SZ) / GBM);
    gemm_xw<<<ggrid, 256>>>(x, W, states);

    recur_kernel<<<RBLK, 512, RECUR_SMEM>>>(states, hfinal, U, b, tau);
}

// round 16
// speedup vs baseline: 1.2220x; 1.0170x over previous
#include <cuda_runtime.h>
#include <math.h>

#define B_SZ 32
#define T_SZ 1024
#define I_SZ 512
#define H_SZ 1024
#define DT_C 0.1f

typedef unsigned long long ull;

// ---------------- f32x2 packed-math helpers (Blackwell FFMA2) -------------
__device__ __forceinline__ ull ffma2(ull a, ull b, ull c) {
    ull d; asm("fma.rn.f32x2 %0, %1, %2, %3;" : "=l"(d) : "l"(a), "l"(b), "l"(c)); return d;
}
__device__ __forceinline__ ull fadd2(ull a, ull b) {
    ull d; asm("add.rn.f32x2 %0, %1, %2;" : "=l"(d) : "l"(a), "l"(b)); return d;
}
__device__ __forceinline__ ull pack2(float lo, float hi) {
    ull d; asm("mov.b64 %0, {%1, %2};" : "=l"(d) : "f"(lo), "f"(hi)); return d;
}
__device__ __forceinline__ float2 unpack2(ull v) {
    float2 r; asm("mov.b64 {%0, %1}, %2;" : "=f"(r.x), "=f"(r.y) : "l"(v)); return r;
}
// Acquire load for producer-flag polls (orders subsequent loads after flag).
__device__ __forceinline__ int ld_acq(const volatile int* p) {
    int v;
    asm volatile("ld.acquire.gpu.global.s32 %0, [%1];"
                 : "=r"(v) : "l"((const int*)p) : "memory");
    return v;
}

// ------------------------------------------------------------------
// Persistent-kernel global state
// g_hT: TRIPLE-buffered transposed hidden state: [3][H][B]  (k-major).
// Depth-3: the write at step t (buf (t+1)%3) only conflicts with reads
// at step t-2, which the staging poll (g_arrive[peer] >= t) already
// excludes -> no write-permission flags needed (R13-proven).
// g_arrive[blk]: h for step t+1 published (set end of step t).
// ------------------------------------------------------------------
#define RBLK 128
#define FPAD 32                      // ints per flag slot (128B line)
__device__ float g_hT[3][H_SZ * B_SZ];
__device__ volatile int g_arrive[RBLK * FPAD];

__global__ void reset_kernel() {
    int idx = blockIdx.x * blockDim.x + threadIdx.x;
    if (idx < H_SZ * B_SZ) g_hT[0][idx] = 0.0f;
    if (idx < RBLK * FPAD) g_arrive[idx] = 0;
}

// ------------------------------------------------------------------
// xW GEMM: C[M=B*T, H] = X[M, I] @ W[H, I]^T   (fp32, FFMA2 inner)
// 128x64 block tile, BK=16, 256 threads  (R8/R11-proven)
// ------------------------------------------------------------------
#define GBM 128
#define GBN 64
#define GBK 16

union F4U { float4 f4; ull u[2]; };

__global__ void __launch_bounds__(256) gemm_xw(
    const float* __restrict__ X, const float* __restrict__ W,
    float* __restrict__ C)
{
    __shared__ float Xs[GBK][GBM];
    __shared__ float Ws[GBK][GBN + 4];
    const int tid = threadIdx.x;
    const int tx = tid & 15;   // 16 -> N
    const int ty = tid >> 4;   // 16 -> M
    const int m0 = blockIdx.y * GBM;
    const int n0 = blockIdx.x * GBN;

    ull acc2[4][4];   // [m-pair p][n j]
#pragma unroll
    for (int p = 0; p < 4; p++)
#pragma unroll
        for (int j = 0; j < 4; j++) acc2[p][j] = 0ull;

    for (int k0 = 0; k0 < I_SZ; k0 += GBK) {
#pragma unroll
        for (int pp = 0; pp < 2; pp++) {
            int q = tid + pp * 256;
            int row = q >> 2, qc = q & 3;
            float4 v = *(const float4*)(X + (size_t)(m0 + row) * I_SZ + k0 + qc * 4);
            Xs[qc * 4 + 0][row] = v.x; Xs[qc * 4 + 1][row] = v.y;
            Xs[qc * 4 + 2][row] = v.z; Xs[qc * 4 + 3][row] = v.w;
        }
        {
            int row = tid >> 2, qc = tid & 3;
            float4 v = *(const float4*)(W + (size_t)(n0 + row) * I_SZ + k0 + qc * 4);
            Ws[qc * 4 + 0][row] = v.x; Ws[qc * 4 + 1][row] = v.y;
            Ws[qc * 4 + 2][row] = v.z; Ws[qc * 4 + 3][row] = v.w;
        }
        __syncthreads();
#pragma unroll
        for (int kk = 0; kk < GBK; kk++) {
            F4U a0, a1;
            a0.f4 = *(const float4*)&Xs[kk][ty * 8];
            a1.f4 = *(const float4*)&Xs[kk][ty * 8 + 4];
            float4 bv = *(const float4*)&Ws[kk][tx * 4];
            ull bd[4];
            bd[0] = pack2(bv.x, bv.x); bd[1] = pack2(bv.y, bv.y);
            bd[2] = pack2(bv.z, bv.z); bd[3] = pack2(bv.w, bv.w);
            ull a2[4] = {a0.u[0], a0.u[1], a1.u[0], a1.u[1]};
#pragma unroll
            for (int p = 0; p < 4; p++)
#pragma unroll
                for (int j = 0; j < 4; j++)
                    acc2[p][j] = ffma2(a2[p], bd[j], acc2[p][j]);
        }
        __syncthreads();
    }
#pragma unroll
    for (int p = 0; p < 4; p++) {
        float2 c0 = unpack2(acc2[p][0]);
        float2 c1 = unpack2(acc2[p][1]);
        float2 c2 = unpack2(acc2[p][2]);
        float2 c3 = unpack2(acc2[p][3]);
        float4 lo = make_float4(c0.x, c1.x, c2.x, c3.x);
        float4 hi = make_float4(c0.y, c1.y, c2.y, c3.y);
        *(float4*)(C + (size_t)(m0 + ty * 8 + 2 * p)     * H_SZ + n0 + tx * 4) = lo;
        *(float4*)(C + (size_t)(m0 + ty * 8 + 2 * p + 1) * H_SZ + n0 + tx * 4) = hi;
    }
}

// ------------------------------------------------------------------
// Persistent recurrence kernel (R13 verbatim + early-flag epilogue).
// grid = 128 blocks (64 j-tiles x 2 b-halves), 512 threads.
// Per step: [stage | sync | compute | STS | sync |
//            w0-3: reduce + publish + flag + deferred stores
//            (w4-15 fall through to next iteration's staging)]
// ------------------------------------------------------------------
#define JT 16
#define BHALF 16
#define USTR 1025
#define HSTR 20
#define NPO 128
#define RECUR_SMEM ((JT * USTR + H_SZ * HSTR) * 4 + NPO * 64 * 8)

__device__ __forceinline__ void stage_chunk(float* hs, int gbase, int bg0,
                                            int ch, int lc, int t_tgt,
                                            int buf) {
    const volatile int* pf = &g_arrive[(gbase | ch) * FPAD];
    while (ld_acq(pf) < t_tgt) { }
    const float* gsrc = g_hT[buf] + bg0 + (size_t)(16 * ch) * B_SZ;
    float* hdst = hs + (16 * ch) * HSTR;
#pragma unroll
    for (int i = 0; i < 8; i++) {
        int f = lc + 8 * i;                 // 0..63 float4s in chunk
        int row = f >> 2, part = (f & 3) * 4;
        float4 v = __ldcg((const float4*)(gsrc + (size_t)row * B_SZ + part));
        float* d = hdst + row * HSTR + part;
        d[0] = v.x; d[1] = v.y; d[2] = v.z; d[3] = v.w;
    }
}

__global__ void __launch_bounds__(512, 1) recur_kernel(
    float* __restrict__ states,      // [B, T, H] (holds xW on entry, states on exit)
    float* __restrict__ hfinal,      // [B, H]
    const float* __restrict__ U,     // [H, H]
    const float* __restrict__ bias,  // [H]
    const float* __restrict__ tau)   // [H]
{
    extern __shared__ float sm[];
    float* Us = sm;                                 // [JT][USTR]
    float* hs = Us + JT * USTR;                     // [1024][HSTR]
    ull* red = (ull*)(hs + H_SZ * HSTR);            // [NPO][64]

    const int tid = threadIdx.x;
    const int blk = blockIdx.x;
    const int jt = blk & 63;
    const int bh = blk >> 6;
    const int j0 = jt * JT;
    const int bg0 = bh * BHALF;
    const int gbase = bh << 6;        // first block of this flag group

    const int tb = tid & 1;
    const int tj = (tid >> 1) & 3;
    const int ks = tid >> 3;      // 0..63

    // ---- staging chunk assignment (R13-proven split) ----
    // warps 0-3  (tid < 128): chunks jt..jt+15 (incl. self; staged after
    //   the epilogue -- self flag is set by then)
    // warps 4-15 (tid >=128): chunks jt+16..jt+63 (staged during the
    //   epilogue of warps 0-3)
    const int ch = (tid < 128) ? ((jt + (tid >> 3)) & 63)
                               : ((jt + 16 + ((tid - 128) >> 3)) & 63);
    const int lc = tid & 7;

    // ---- load U slab into smem: Us[row][k], row = 0..15 ----
    for (int q = tid; q < JT * (H_SZ / 4); q += 512) {
        int row = q >> 8;
        int c = (q & 255) * 4;
        float4 v = *(const float4*)(U + (size_t)(j0 + row) * H_SZ + c);
        float* d = Us + row * USTR + c;
        d[0] = v.x; d[1] = v.y; d[2] = v.z; d[3] = v.w;
    }

    // ---- epilogue (reader) setup: tid < 128, sr = tid & 15 ----
    int po = 0, sr = 0, jg = 0, bp = 0;
    float decay = 0.0f, biasj = 0.0f;
    size_t sidx0 = 0, sidx1 = 0;
    float xwA = 0.0f, xwB = 0.0f;
    if (tid < NPO) {
        int r = tid;
        po = ((r >> 1) & 1) | ((r & 1) << 1) | (((r >> 4) & 1) << 2)
           | (((r >> 5) & 1) << 3) | (((r >> 6) & 1) << 4)
           | (((r >> 2) & 1) << 5) | (((r >> 3) & 1) << 6);
        sr = r & 15;
        int j_loc = po >> 3;
        bp = po & 7;
        jg = j0 + j_loc;
        float it = 1.0f / tau[jg];
        decay = 1.0f - DT_C * it;
        biasj = bias[jg];
        int b_glob = bg0 + 2 * bp;
        sidx0 = (size_t)b_glob * T_SZ * H_SZ + jg;
        sidx1 = sidx0 + (size_t)T_SZ * H_SZ;
        xwA = __ldcg(states + sidx0);   // prefetch t = 0
        xwB = __ldcg(states + sidx1);
    }

    int cur = 0;    // buffer index = t % 3
    __syncthreads();

    for (int t = 0; t < T_SZ; t++) {
        // ---- stage h for step t from g_hT[cur]; per-chunk producer poll --
        stage_chunk(hs, gbase, bg0, ch, lc, t, cur);
        __syncthreads();

        // ---- compute: acc2[jj][m] over k = ks + 64*kq ----
        ull acc2[4][4];
#pragma unroll
        for (int jj = 0; jj < 4; jj++)
#pragma unroll
            for (int m = 0; m < 4; m++) acc2[jj][m] = 0ull;

        const float* urow = Us + tj * 4 * USTR + ks;
#pragma unroll
        for (int kq = 0; kq < 16; kq++) {
            int k = ks + 64 * kq;
            const float* hrow = hs + k * HSTR + 2 * tb;
            ull h0 = *(const ull*)(hrow + 0);
            ull h1 = *(const ull*)(hrow + 4);
            ull h2 = *(const ull*)(hrow + 8);
            ull h3 = *(const ull*)(hrow + 12);
#pragma unroll
            for (int jj = 0; jj < 4; jj++) {
                float us = urow[jj * USTR + 64 * kq];
                ull ud = pack2(us, us);
                acc2[jj][0] = ffma2(ud, h0, acc2[jj][0]);
                acc2[jj][1] = ffma2(ud, h1, acc2[jj][1]);
                acc2[jj][2] = ffma2(ud, h2, acc2[jj][2]);
                acc2[jj][3] = ffma2(ud, h3, acc2[jj][3]);
            }
        }

        // ---- write partials, XOR-swizzled (2-phase-optimal STS.64) ----
#pragma unroll
        for (int jj = 0; jj < 4; jj++)
#pragma unroll
            for (int m = 0; m < 4; m++) {
                int p = (tj * 4 + jj) * 8 + 2 * m + tb;
                int col = ks ^ ((m & 1) | (tb << 1) | (tj << 2));
                red[p * 64 + col] = acc2[jj][m];
            }
        __syncthreads();
        // After this sync, warps 4-15 are DONE with step t: they fall
        // through to the next iteration's staging (overlapping the
        // epilogue). hs chunks they overwrite are gated on their
        // producers' t+1 flags; warps 0-3 below read only red + the own
        // chunk (jt), whose flag is set only after this epilogue.

        int nxt = cur + 1; if (nxt == 3) nxt = 0;
        if (tid < NPO) {
            // ---- reduce ----
            ull s01 = 0ull, s23 = 0ull;
#pragma unroll
            for (int i = 0; i < 64; i += 2) {
                s01 = fadd2(s01, red[po * 64 + (i ^ sr)]);
                s23 = fadd2(s23, red[po * 64 + ((i + 1) ^ sr)]);
            }
            float2 sum = unpack2(fadd2(s01, s23));
            float2 hold = *(const float2*)(hs + jg * HSTR + 2 * bp);
            // ---- pointwise epilogue ----
            float a0 = tanhf(xwA + sum.x + biasj);
            float a1 = tanhf(xwB + sum.y + biasj);
            float h0n = decay * hold.x + DT_C * a0;
            float h1n = decay * hold.y + DT_C * a1;
            float2 hn = make_float2(h0n, h1n);
            // peer-visible publish FIRST, then flag ASAP (early flag)
            __stcg((float2*)(g_hT[nxt] + (size_t)jg * B_SZ + bg0 + 2 * bp), hn);
            asm volatile("bar.sync 1, 128;" ::: "memory");
            if (tid == 0) {
                __threadfence();
                g_arrive[blk * FPAD] = t + 1;
            }
            // deferred non-shared outputs (nothing reads these this step)
            size_t off = (size_t)t * H_SZ;
            __stcg(states + sidx0 + off, h0n);
            __stcg(states + sidx1 + off, h1n);
            if (t == T_SZ - 1) {
                __stcg(hfinal + (size_t)(bg0 + 2 * bp) * H_SZ + jg, h0n);
                __stcg(hfinal + (size_t)(bg0 + 2 * bp + 1) * H_SZ + jg, h1n);
            } else {
                xwA = __ldcg(states + sidx0 + off + H_SZ);   // prefetch t+1
                xwB = __ldcg(states + sidx1 + off + H_SZ);
            }
        }
        cur = nxt;
    }
}

// ------------------------------------------------------------------
// Launcher
// ------------------------------------------------------------------
extern "C" void kernel_launch(void* const* d_in, const int* in_sizes, int n_in,
                              void* d_out, int out_size) {
    const float* x   = (const float*)d_in[0];   // [B, T, I]
    const float* W   = (const float*)d_in[1];   // [H, I]
    const float* U   = (const float*)d_in[2];   // [H, H]
    const float* b   = (const float*)d_in[3];   // [H]
    const float* tau = (const float*)d_in[4];   // [H]

    float* hfinal = (float*)d_out;              // [B, H]
    float* states = hfinal + B_SZ * H_SZ;       // [B, T, H]

    cudaFuncSetAttribute(recur_kernel,
                         cudaFuncAttributeMaxDynamicSharedMemorySize,
                         RECUR_SMEM);

    reset_kernel<<<32, 1024>>>();

    dim3 ggrid(H_SZ / GBN, (B_SZ * T_SZ) / GBM);
    gemm_xw<<<ggrid, 256>>>(x, W, states);

    recur_kernel<<<RBLK, 512, RECUR_SMEM>>>(states, hfinal, U, b, tau);
}

// round 17
// speedup vs baseline: 1.2819x; 1.0490x over previous
#include <cuda_runtime.h>
#include <math.h>

#define B_SZ 32
#define T_SZ 1024
#define I_SZ 512
#define H_SZ 1024
#define DT_C 0.1f

typedef unsigned long long ull;

// ---------------- f32x2 packed-math helpers (Blackwell FFMA2) -------------
__device__ __forceinline__ ull ffma2(ull a, ull b, ull c) {
    ull d; asm("fma.rn.f32x2 %0, %1, %2, %3;" : "=l"(d) : "l"(a), "l"(b), "l"(c)); return d;
}
__device__ __forceinline__ ull fadd2(ull a, ull b) {
    ull d; asm("add.rn.f32x2 %0, %1, %2;" : "=l"(d) : "l"(a), "l"(b)); return d;
}
__device__ __forceinline__ ull pack2(float lo, float hi) {
    ull d; asm("mov.b64 %0, {%1, %2};" : "=l"(d) : "f"(lo), "f"(hi)); return d;
}
__device__ __forceinline__ float2 unpack2(ull v) {
    float2 r; asm("mov.b64 {%0, %1}, %2;" : "=f"(r.x), "=f"(r.y) : "l"(v)); return r;
}
// Acquire load for producer-flag polls (orders subsequent loads after flag).
__device__ __forceinline__ int ld_acq(const volatile int* p) {
    int v;
    asm volatile("ld.acquire.gpu.global.s32 %0, [%1];"
                 : "=r"(v) : "l"((const int*)p) : "memory");
    return v;
}

// ------------------------------------------------------------------
// Persistent-kernel global state
// g_hT: TRIPLE-buffered transposed hidden state: [3][H][B]  (k-major).
// Depth-3: the write at step t (buf (t+1)%3) only conflicts with reads
// at step t-2, which the staging poll (g_arrive[peer] >= t) already
// excludes (R13-proven). g_arrive[blk]: h for step t+1 published.
// ------------------------------------------------------------------
#define RBLK 128
#define FPAD 32                      // ints per flag slot (128B line)
__device__ float g_hT[3][H_SZ * B_SZ];
__device__ volatile int g_arrive[RBLK * FPAD];

__global__ void reset_kernel() {
    int idx = blockIdx.x * blockDim.x + threadIdx.x;
    if (idx < H_SZ * B_SZ) g_hT[0][idx] = 0.0f;
    if (idx < RBLK * FPAD) g_arrive[idx] = 0;
}

// ------------------------------------------------------------------
// xW GEMM: C[M=B*T, H] = X[M, I] @ W[H, I]^T   (fp32, FFMA2 inner)
// 128x64 block tile, BK=16, 256 threads  (R8/R11-proven)
// ------------------------------------------------------------------
#define GBM 128
#define GBN 64
#define GBK 16

union F4U { float4 f4; ull u[2]; };

__global__ void __launch_bounds__(256) gemm_xw(
    const float* __restrict__ X, const float* __restrict__ W,
    float* __restrict__ C)
{
    __shared__ float Xs[GBK][GBM];
    __shared__ float Ws[GBK][GBN + 4];
    const int tid = threadIdx.x;
    const int tx = tid & 15;   // 16 -> N
    const int ty = tid >> 4;   // 16 -> M
    const int m0 = blockIdx.y * GBM;
    const int n0 = blockIdx.x * GBN;

    ull acc2[4][4];   // [m-pair p][n j]
#pragma unroll
    for (int p = 0; p < 4; p++)
#pragma unroll
        for (int j = 0; j < 4; j++) acc2[p][j] = 0ull;

    for (int k0 = 0; k0 < I_SZ; k0 += GBK) {
#pragma unroll
        for (int pp = 0; pp < 2; pp++) {
            int q = tid + pp * 256;
            int row = q >> 2, qc = q & 3;
            float4 v = *(const float4*)(X + (size_t)(m0 + row) * I_SZ + k0 + qc * 4);
            Xs[qc * 4 + 0][row] = v.x; Xs[qc * 4 + 1][row] = v.y;
            Xs[qc * 4 + 2][row] = v.z; Xs[qc * 4 + 3][row] = v.w;
        }
        {
            int row = tid >> 2, qc = tid & 3;
            float4 v = *(const float4*)(W + (size_t)(n0 + row) * I_SZ + k0 + qc * 4);
            Ws[qc * 4 + 0][row] = v.x; Ws[qc * 4 + 1][row] = v.y;
            Ws[qc * 4 + 2][row] = v.z; Ws[qc * 4 + 3][row] = v.w;
        }
        __syncthreads();
#pragma unroll
        for (int kk = 0; kk < GBK; kk++) {
            F4U a0, a1;
            a0.f4 = *(const float4*)&Xs[kk][ty * 8];
            a1.f4 = *(const float4*)&Xs[kk][ty * 8 + 4];
            float4 bv = *(const float4*)&Ws[kk][tx * 4];
            ull bd[4];
            bd[0] = pack2(bv.x, bv.x); bd[1] = pack2(bv.y, bv.y);
            bd[2] = pack2(bv.z, bv.z); bd[3] = pack2(bv.w, bv.w);
            ull a2[4] = {a0.u[0], a0.u[1], a1.u[0], a1.u[1]};
#pragma unroll
            for (int p = 0; p < 4; p++)
#pragma unroll
                for (int j = 0; j < 4; j++)
                    acc2[p][j] = ffma2(a2[p], bd[j], acc2[p][j]);
        }
        __syncthreads();
    }
#pragma unroll
    for (int p = 0; p < 4; p++) {
        float2 c0 = unpack2(acc2[p][0]);
        float2 c1 = unpack2(acc2[p][1]);
        float2 c2 = unpack2(acc2[p][2]);
        float2 c3 = unpack2(acc2[p][3]);
        float4 lo = make_float4(c0.x, c1.x, c2.x, c3.x);
        float4 hi = make_float4(c0.y, c1.y, c2.y, c3.y);
        *(float4*)(C + (size_t)(m0 + ty * 8 + 2 * p)     * H_SZ + n0 + tx * 4) = lo;
        *(float4*)(C + (size_t)(m0 + ty * 8 + 2 * p + 1) * H_SZ + n0 + tx * 4) = hi;
    }
}

// ------------------------------------------------------------------
// Persistent recurrence kernel — CHUNK-LOCAL dataflow version.
// grid = 128 blocks (64 j-tiles x 2 b-halves), 512 threads.
// Thread (tb,tj,ks): stages (with its 8-thread team) AND computes over
// chunk ks (k rows 16ks..16ks+15). stage->compute gating is per-team
// (__syncwarp), not block-wide: early chunks compute while late
// producers straggle.
// red protected across steps by split named barrier 2:
//   w0-3: bar.arrive 2,512 right after reduce reads (pre-armed once);
//   w4-15: bar.sync 2,512 before their next-step STS.
// ------------------------------------------------------------------
#define JT 16
#define BHALF 16
#define USTR 1025
#define CHSTR 328                // 16 rows x 20 + 8 pad (bank-staggers chunks)
#define NPO 128
#define RECUR_SMEM ((JT * USTR + 64 * CHSTR) * 4 + NPO * 64 * 8)

__device__ __forceinline__ void stage_chunk(float* hs, int gbase, int bg0,
                                            int ch, int lc, int t_tgt,
                                            int buf) {
    const volatile int* pf = &g_arrive[(gbase | ch) * FPAD];
    while (ld_acq(pf) < t_tgt) { }
    const float* gsrc = g_hT[buf] + bg0 + (size_t)(16 * ch) * B_SZ;
    float* hdst = hs + ch * CHSTR;
#pragma unroll
    for (int i = 0; i < 8; i++) {
        int f = lc + 8 * i;                 // 0..63 float4s in chunk
        int row = f >> 2, part = (f & 3) * 4;
        float4 v = __ldcg((const float4*)(gsrc + (size_t)row * B_SZ + part));
        float* d = hdst + row * 20 + part;
        d[0] = v.x; d[1] = v.y; d[2] = v.z; d[3] = v.w;
    }
}

__global__ void __launch_bounds__(512, 1) recur_kernel(
    float* __restrict__ states,      // [B, T, H] (holds xW on entry, states on exit)
    float* __restrict__ hfinal,      // [B, H]
    const float* __restrict__ U,     // [H, H]
    const float* __restrict__ bias,  // [H]
    const float* __restrict__ tau)   // [H]
{
    extern __shared__ float sm[];
    float* Us = sm;                                 // [JT][USTR]
    float* hs = Us + JT * USTR;                     // [64][CHSTR] chunk-padded
    ull* red = (ull*)(hs + 64 * CHSTR);             // [NPO][64]

    const int tid = threadIdx.x;
    const int blk = blockIdx.x;
    const int jt = blk & 63;
    const int bh = blk >> 6;
    const int j0 = jt * JT;
    const int bg0 = bh * BHALF;
    const int gbase = bh << 6;        // first block of this flag group

    const int tb = tid & 1;
    const int tj = (tid >> 1) & 3;
    const int ks = tid >> 3;      // 0..63 = this thread's chunk (stage+compute)
    const int lc = tid & 7;       // lane within 8-thread chunk team

    // ---- load U slab into smem: Us[row][k], row = 0..15 ----
    for (int q = tid; q < JT * (H_SZ / 4); q += 512) {
        int row = q >> 8;
        int c = (q & 255) * 4;
        float4 v = *(const float4*)(U + (size_t)(j0 + row) * H_SZ + c);
        float* d = Us + row * USTR + c;
        d[0] = v.x; d[1] = v.y; d[2] = v.z; d[3] = v.w;
    }

    // ---- epilogue (reader) setup: tid < 128, sr = tid & 15 ----
    int po = 0, sr = 0, jg = 0, bp = 0, j_loc = 0;
    float decay = 0.0f, biasj = 0.0f;
    size_t sidx0 = 0, sidx1 = 0;
    float xwA = 0.0f, xwB = 0.0f;
    if (tid < NPO) {
        int r = tid;
        po = ((r >> 1) & 1) | ((r & 1) << 1) | (((r >> 4) & 1) << 2)
           | (((r >> 5) & 1) << 3) | (((r >> 6) & 1) << 4)
           | (((r >> 2) & 1) << 5) | (((r >> 3) & 1) << 6);
        sr = r & 15;
        j_loc = po >> 3;
        bp = po & 7;
        jg = j0 + j_loc;
        float it = 1.0f / tau[jg];
        decay = 1.0f - DT_C * it;
        biasj = bias[jg];
        int b_glob = bg0 + 2 * bp;
        sidx0 = (size_t)b_glob * T_SZ * H_SZ + jg;
        sidx1 = sidx0 + (size_t)T_SZ * H_SZ;
        xwA = __ldcg(states + sidx0);   // prefetch t = 0
        xwB = __ldcg(states + sidx1);
    }

    int cur = 0;    // buffer index = t % 3
    __syncthreads();

    // pre-arm barrier 2 so w4-15's first bar.sync passes (pipelined phase)
    if (tid < NPO) {
        asm volatile("bar.arrive 2, 512;" ::: "memory");
    }

    for (int t = 0; t < T_SZ; t++) {
        // ---- stage OWN chunk (team of 8); gated on its producer only ----
        stage_chunk(hs, gbase, bg0, ks, lc, t, cur);
        __syncwarp();   // team's staged data visible to team's compute

        // ---- compute over own chunk: k = 16*ks + kk ----
        ull acc2[4][4];
#pragma unroll
        for (int jj = 0; jj < 4; jj++)
#pragma unroll
            for (int m = 0; m < 4; m++) acc2[jj][m] = 0ull;

        const float* ubase = Us + (tj * 4) * USTR + 16 * ks;
        const float* hbase = hs + ks * CHSTR + 2 * tb;
#pragma unroll
        for (int kk = 0; kk < 16; kk++) {
            const float* hrow = hbase + kk * 20;
            ull h0 = *(const ull*)(hrow + 0);
            ull h1 = *(const ull*)(hrow + 4);
            ull h2 = *(const ull*)(hrow + 8);
            ull h3 = *(const ull*)(hrow + 12);
#pragma unroll
            for (int jj = 0; jj < 4; jj++) {
                float us = ubase[jj * USTR + kk];
                ull ud = pack2(us, us);
                acc2[jj][0] = ffma2(ud, h0, acc2[jj][0]);
                acc2[jj][1] = ffma2(ud, h1, acc2[jj][1]);
                acc2[jj][2] = ffma2(ud, h2, acc2[jj][2]);
                acc2[jj][3] = ffma2(ud, h3, acc2[jj][3]);
            }
        }

        // ---- w4-15: wait until w0-3 finished reading red for step t-1 ----
        if (tid >= 128) {
            asm volatile("bar.sync 2, 512;" ::: "memory");
        }

        // ---- write partials, XOR-swizzled (2-phase-optimal STS.64) ----
#pragma unroll
        for (int jj = 0; jj < 4; jj++)
#pragma unroll
            for (int m = 0; m < 4; m++) {
                int p = (tj * 4 + jj) * 8 + 2 * m + tb;
                int col = ks ^ ((m & 1) | (tb << 1) | (tj << 2));
                red[p * 64 + col] = acc2[jj][m];
            }
        __syncthreads();
        // Warps 4-15 fall through to iteration t+1: stage (flag-gated) and
        // compute overlap w0-3's reduce+epilogue below; their next STS is
        // blocked by bar2 until w0-3's arrive (after reduce reads).

        int nxt = cur + 1; if (nxt == 3) nxt = 0;
        if (tid < NPO) {
            // ---- reduce ----
            ull s01 = 0ull, s23 = 0ull;
#pragma unroll
            for (int i = 0; i < 64; i += 2) {
                s01 = fadd2(s01, red[po * 64 + (i ^ sr)]);
                s23 = fadd2(s23, red[po * 64 + ((i + 1) ^ sr)]);
            }
            float2 sum = unpack2(fadd2(s01, s23));
            // hold from own chunk jt (chunk-padded address)
            float2 hold = *(const float2*)(hs + jt * CHSTR + j_loc * 20 + 2 * bp);
            // red + hold reads done: release w4-15 for their next STS
            asm volatile("bar.arrive 2, 512;" ::: "memory");
            // ---- pointwise epilogue (R13-proven order) ----
            float a0 = tanhf(xwA + sum.x + biasj);
            float a1 = tanhf(xwB + sum.y + biasj);
            float h0n = decay * hold.x + DT_C * a0;
            float h1n = decay * hold.y + DT_C * a1;
            size_t off = (size_t)t * H_SZ;
            __stcg(states + sidx0 + off, h0n);
            __stcg(states + sidx1 + off, h1n);
            float2 hn = make_float2(h0n, h1n);
            __stcg((float2*)(g_hT[nxt] + (size_t)jg * B_SZ + bg0 + 2 * bp), hn);
            if (t == T_SZ - 1) {
                __stcg(hfinal + (size_t)(bg0 + 2 * bp) * H_SZ + jg, h0n);
                __stcg(hfinal + (size_t)(bg0 + 2 * bp + 1) * H_SZ + jg, h1n);
            } else {
                xwA = __ldcg(states + sidx0 + off + H_SZ);   // prefetch t+1
                xwB = __ldcg(states + sidx1 + off + H_SZ);
            }
            // order all 128 epilogue threads' publishes before the flag
            asm volatile("bar.sync 1, 128;" ::: "memory");
            if (tid == 0) {
                __threadfence();
                g_arrive[blk * FPAD] = t + 1;
            }
        }
        cur = nxt;
    }
}

// ------------------------------------------------------------------
// Launcher
// ------------------------------------------------------------------
extern "C" void kernel_launch(void* const* d_in, const int* in_sizes, int n_in,
                              void* d_out, int out_size) {
    const float* x   = (const float*)d_in[0];   // [B, T, I]
    const float* W   = (const float*)d_in[1];   // [H, I]
    const float* U   = (const float*)d_in[2];   // [H, H]
    const float* b   = (const float*)d_in[3];   // [H]
    const float* tau = (const float*)d_in[4];   // [H]

    float* hfinal = (float*)d_out;              // [B, H]
    float* states = hfinal + B_SZ * H_SZ;       // [B, T, H]

    cudaFuncSetAttribute(recur_kernel,
                         cudaFuncAttributeMaxDynamicSharedMemorySize,
                         RECUR_SMEM);

    reset_kernel<<<32, 1024>>>();

    dim3 ggrid(H_SZ / GBN, (B_SZ * T_SZ) / GBM);
    gemm_xw<<<ggrid, 256>>>(x, W, states);

    recur_kernel<<<RBLK, 512, RECUR_SMEM>>>(states, hfinal, U, b, tau);
}